// round 9
// baseline (speedup 1.0000x reference)
#include <cuda_runtime.h>

#define TLEN   2048
#define BATCH  8192
#define CCH    4                    // chunks per row
#define CHUNK  (TLEN / CCH)         // 512
#define WARM   128                  // warm-start steps
#define TILE   16                   // steps per round
#define ROUNDS ((CHUNK + WARM) / TILE)  // 40
#define WROUND (WARM / TILE)        // 8
#define BLOCKT 256                  // 64 rows x 4 chunks
#define ROWSPB 64
#define NBLK   (BATCH / ROWSPB)     // 128

// smem: inputs [2 buf][3 in][4 slot][256 thr] float4 = 96KB, then staging 256x144B
#define ST_BASE    98304
#define ST_STRIDE  144
#define SMEM_BYTES (ST_BASE + 256 * ST_STRIDE)   // 135168

__device__ __forceinline__ float frcp_fast(float x) {
    float r; asm("rcp.approx.f32 %0, %1;" : "=f"(r) : "f"(x)); return r;
}
__device__ __forceinline__ float ftanh_fast(float x) {
    float r; asm("tanh.approx.f32 %0, %1;" : "=f"(r) : "f"(x)); return r;
}
__device__ __forceinline__ void cpasync16(void* dst, const void* src) {
    unsigned d = (unsigned)__cvta_generic_to_shared(dst);
    asm volatile("cp.async.cg.shared.global [%0], [%1], 16;" :: "r"(d), "l"(src) : "memory");
}
__device__ __forceinline__ void cp_commit() {
    asm volatile("cp.async.commit_group;" ::: "memory");
}

extern __shared__ char sm[];

// coalesced tile load: 12 LDGSTS/thread; each thread owns slot=tid&3, target chunk=(tid>>2)&3
__device__ __forceinline__ void issue_tile(int k, int buf, int row0, int tid,
                                           const float* __restrict__ P,
                                           const float* __restrict__ H,
                                           const float* __restrict__ S)
{
    const int slot = tid & 3;
    const int ccT  = (tid >> 2) & 3;          // chunk of the TARGET segment
    const int rb   = tid >> 4;
    int t0 = ccT * CHUNK - WARM + TILE * k;
    if (t0 < 0) t0 = 0;                       // chunk 0 warmup clamp (garbage, reset later)

    #pragma unroll
    for (int I = 0; I < 3; I++) {
        const float* base = (I == 0) ? P : (I == 1) ? H : S;
        #pragma unroll
        for (int bq = 0; bq < 4; bq++) {
            const int rr  = bq * 16 + rb;                 // target row-in-block
            const int seg = bq * 64 + (tid >> 2);         // target thread
            const float* src = base + (size_t)(row0 + rr) * TLEN + t0 + slot * 4;
            char* dst = sm + (size_t)((((buf * 3 + I) * 4 + slot) * 256 + seg) * 16);
            cpasync16(dst, src);
        }
    }
    cp_commit();
}

// 4 EKF steps; carried chain S@12 -> rcp@28 -> P'@32
__device__ __forceinline__ void steps4(const float4 pv, const float4 hv, const float4 sv,
                                       float& p00, float& p01, float& p11,
                                       float& x0, float& x1, float4* st)
{
    const float zz[4] = {pv.x, pv.y, pv.z, pv.w};
    const float hh[4] = {hv.x, hv.y, hv.z, hv.w};
    const float ss[4] = {sv.x, sv.y, sv.z, sv.w};
    float4 o;
    #pragma unroll
    for (int j = 0; j < 4; j++) {
        const float a  = fmaf(0.25f, ftanh_fast(fmaf(5.0f, hh[j], -2.5f)), 0.75f);
        const float r  = fmaxf(100.0f * ss[j], 1.0f);
        const float q  = 0.1f * r;
        const float qs = 1.1f * r;
        const float r2 = r * r;

        const float p01n = fmaf(a, p11, p01);
        const float X    = fmaf(a, p01, p00 + qs);
        const float S    = fmaf(a, p01n, X);
        const float Sinv = frcp_fast(S);               // S >= 1

        const float rm   = p01n * r;
        const float n2   = p01n * p01n;
        const float p11n = p11 + q;
        const float xp0  = fmaf(a, x1, x0);
        const float y    = zz[j] - xp0;

        const float K0 = fmaf(-r, Sinv, 1.0f);
        const float K1 = p01n * Sinv;

        p00 = fmaf(-r2, Sinv, r);
        p01 = rm * Sinv;
        p11 = fmaf(-n2, Sinv, p11n);
        x0  = fmaf(K0, y, xp0);
        x1  = fmaf(K1, y, x1);

        if ((j & 1) == 0) { o.x = x0; o.y = x1; }
        else              { o.z = x0; o.w = x1; st[j >> 1] = o; }
    }
}

__global__ void __launch_bounds__(BLOCKT, 1)
ekf_kernel(const float* __restrict__ price,
           const float* __restrict__ hurst,
           const float* __restrict__ sigv,
           float* __restrict__ out)
{
    const int tid  = threadIdx.x;
    const int cown = tid & 3;                 // this thread's chunk
    const int row0 = blockIdx.x * ROWSPB;
    const float4* in4 = (const float4*)sm;

    // prologue: tile 0
    issue_tile(0, 0, row0, tid, price, hurst, sigv);
    asm volatile("cp.async.wait_group 0;" ::: "memory");
    __syncthreads();

    // init from own tile-0 price values (for chunk 0 these are z[0], z[1])
    float4 pz = in4[(0 * 4 + 0) * 256 + tid];
    float x0 = pz.x;
    float x1 = pz.y - pz.x;
    float p00 = 1.0f, p01 = 0.0f, p11 = 1.0f;

    #pragma unroll 1
    for (int k = 0; k < ROUNDS; k++) {
        const int buf = k & 1;
        if (k + 1 < ROUNDS) issue_tile(k + 1, buf ^ 1, row0, tid, price, hurst, sigv);
        else                cp_commit();      // empty group keeps wait count uniform
        asm volatile("cp.async.wait_group 1;" ::: "memory");
        __syncthreads();                      // tile k visible to all; staging free

        // chunk 0: replace garbage warmup with the exact reference init at t=0
        if (k == WROUND && cown == 0) {
            const float4 p0 = in4[((buf * 3 + 0) * 4 + 0) * 256 + tid];
            x0 = p0.x; x1 = p0.y - p0.x;
            p00 = 1.0f; p01 = 0.0f; p11 = 1.0f;
        }

        // compute 16 steps, staging outputs (own segment only)
        {
            char* stRow = sm + ST_BASE + tid * ST_STRIDE;
            #pragma unroll
            for (int s = 0; s < 4; s++) {
                const float4 pv = in4[((buf * 3 + 0) * 4 + s) * 256 + tid];
                const float4 hv = in4[((buf * 3 + 1) * 4 + s) * 256 + tid];
                const float4 sv = in4[((buf * 3 + 2) * 4 + s) * 256 + tid];
                steps4(pv, hv, sv, p00, p01, p11, x0, x1, (float4*)(stRow + s * 32));
            }
        }
        __syncthreads();                      // staging complete

        // flush (post-warmup rounds): 8 x 16B granules/thread, 128B gmem runs
        if (k >= WROUND) {
            const int ccF = (tid >> 3) & 3;
            const int t0o = ccF * CHUNK - WARM + TILE * k;
            #pragma unroll
            for (int b = 0; b < 8; b++) {
                const int seg = b * 32 + (tid >> 3);
                const int rr  = b * 8 + (tid >> 5);
                const float4 v = *(const float4*)(sm + ST_BASE + seg * ST_STRIDE + (tid & 7) * 16);
                *(float4*)((char*)out + (size_t)(row0 + rr) * (TLEN * 8)
                           + (size_t)t0o * 8 + (tid & 7) * 16) = v;
            }
        }
    }
}

extern "C" void kernel_launch(void* const* d_in, const int* in_sizes, int n_in,
                              void* d_out, int out_size)
{
    const float* price = (const float*)d_in[0];
    const float* hurst = (const float*)d_in[1];
    const float* sigv  = (const float*)d_in[2];
    float* out = (float*)d_out;

    static bool attr_set = false;
    if (!attr_set) {
        cudaFuncSetAttribute(ekf_kernel, cudaFuncAttributeMaxDynamicSharedMemorySize, SMEM_BYTES);
        attr_set = true;
    }
    ekf_kernel<<<NBLK, BLOCKT, SMEM_BYTES>>>(price, hurst, sigv, out);
}

// round 10
// speedup vs baseline: 2.0505x; 2.0505x over previous
#include <cuda_runtime.h>

#define TLEN   2048
#define BATCH  8192
#define CCH    4
#define CHUNK  512
#define WARM   128
#define TILE   16
#define ROUNDS ((CHUNK + WARM) / TILE)   // 40
#define WROUND (WARM / TILE)             // 8
#define BLOCKT 256
#define ROWSPB 64                        // 8 warps x 8 rows
#define NBLK   (BATCH / ROWSPB)          // 128

#define IN_VSTR    80                    // vrow stride (64B data + 16 pad): conflict-free LDS.128
#define IN_SLICE   (32 * IN_VSTR)        // 2560 B per (buf, input, warp)
#define STG_BASE   (3 * 3 * 8 * IN_SLICE)   // 184320
#define STG_VSTR   144                   // staging vrow stride (128B data + 16 pad)
#define STG_WARP   (32 * STG_VSTR)       // 4608
#define SMEM_BYTES (STG_BASE + 8 * STG_WARP)  // 221184

__device__ __forceinline__ float frcp_fast(float x) {
    float r; asm("rcp.approx.f32 %0, %1;" : "=f"(r) : "f"(x)); return r;
}
__device__ __forceinline__ float ftanh_fast(float x) {
    float r; asm("tanh.approx.f32 %0, %1;" : "=f"(r) : "f"(x)); return r;
}
__device__ __forceinline__ void cpasync16(void* dst, const void* src) {
    unsigned d = (unsigned)__cvta_generic_to_shared(dst);
    asm volatile("cp.async.cg.shared.global [%0], [%1], 16;" :: "r"(d), "l"(src) : "memory");
}

extern __shared__ char sm[];

// 4 EKF steps; carried chain S@12 -> rcp@28 -> P'@32; outputs packed to staging
__device__ __forceinline__ void steps4(const float4 pv, const float4 hv, const float4 sv,
                                       float& p00, float& p01, float& p11,
                                       float& x0, float& x1, char* stg)
{
    const float zz[4] = {pv.x, pv.y, pv.z, pv.w};
    const float hh[4] = {hv.x, hv.y, hv.z, hv.w};
    const float ss[4] = {sv.x, sv.y, sv.z, sv.w};
    float4 o;
    #pragma unroll
    for (int j = 0; j < 4; j++) {
        const float a  = fmaf(0.25f, ftanh_fast(fmaf(5.0f, hh[j], -2.5f)), 0.75f);
        const float r  = fmaxf(100.0f * ss[j], 1.0f);
        const float q  = 0.1f * r;
        const float qs = 1.1f * r;
        const float r2 = r * r;

        const float p01n = fmaf(a, p11, p01);
        const float X    = fmaf(a, p01, p00 + qs);
        const float S    = fmaf(a, p01n, X);
        const float Sinv = frcp_fast(S);              // S >= 1

        const float rm   = p01n * r;
        const float n2   = p01n * p01n;
        const float p11n = p11 + q;
        const float xp0  = fmaf(a, x1, x0);
        const float y    = zz[j] - xp0;

        const float K0 = fmaf(-r, Sinv, 1.0f);
        const float K1 = p01n * Sinv;

        p00 = fmaf(-r2, Sinv, r);
        p01 = rm * Sinv;
        p11 = fmaf(-n2, Sinv, p11n);
        x0  = fmaf(K0, y, xp0);
        x1  = fmaf(K1, y, x1);

        if ((j & 1) == 0) { o.x = x0; o.y = x1; }
        else { o.z = x0; o.w = x1; *(float4*)(stg + (j >> 1) * 16) = o; }
    }
}

__global__ void __launch_bounds__(BLOCKT, 1)
ekf_kernel(const float* __restrict__ price,
           const float* __restrict__ hurst,
           const float* __restrict__ sigv,
           float* __restrict__ out)
{
    const int tid = threadIdx.x;
    const int w   = tid >> 5;
    const int l   = tid & 31;
    const int cc  = l & 3;                    // this lane's chunk (compute role)
    const int row0 = blockIdx.x * ROWSPB;

    // load-role row (8 rows per warp) and slot
    const size_t lrow = (size_t)(row0 + 8 * w + (l >> 2));
    const float* gP = price + lrow * TLEN;
    const float* gH = hurst + lrow * TLEN;
    const float* gS = sigv  + lrow * TLEN;
    const int ls = l & 3;                     // 16B slot within 64B tile slice

    // per-warp smem bases
    char* stgW = sm + STG_BASE + w * STG_WARP;

    // issue one round's tile for this warp (12 LDGSTS), or an empty group
    auto issue_tile = [&](int k) {
        if (k < ROUNDS) {
            const int buf = k % 3;
            #pragma unroll
            for (int inp = 0; inp < 3; inp++) {
                const float* g = (inp == 0) ? gP : (inp == 1) ? gH : gS;
                char* base = sm + ((buf * 3 + inp) * 8 + w) * IN_SLICE;
                #pragma unroll
                for (int c = 0; c < 4; c++) {
                    int t0 = c * CHUNK - WARM + TILE * k;
                    if (t0 < 0) t0 = 0;       // chunk-0 warmup clamp
                    const int v = (l >> 2) * 4 + c;   // vrow index
                    cpasync16(base + v * IN_VSTR + ls * 16, g + t0 + ls * 4);
                }
            }
        }
        asm volatile("cp.async.commit_group;" ::: "memory");
    };

    // prologue: two rounds in flight
    issue_tile(0);
    issue_tile(1);

    float x0 = 0.f, x1 = 0.f, p00 = 1.0f, p01 = 0.0f, p11 = 1.0f;

    #pragma unroll 1
    for (int k = 0; k < ROUNDS; k++) {
        issue_tile(k + 2);                    // pending: {k, k+1, k+2}
        asm volatile("cp.async.wait_group 2;" ::: "memory");   // tile k landed
        __syncwarp();

        const int buf = k % 3;
        const char* bP = sm + ((buf * 3 + 0) * 8 + w) * IN_SLICE + l * IN_VSTR;
        const char* bH = sm + ((buf * 3 + 1) * 8 + w) * IN_SLICE + l * IN_VSTR;
        const char* bS = sm + ((buf * 3 + 2) * 8 + w) * IN_SLICE + l * IN_VSTR;

        if (k == 0) {
            // init (exact for chunk 0; measurement warm-start for chunks 1-3)
            const float2 pz = *(const float2*)bP;
            x0 = pz.x; x1 = pz.y - pz.x;
            p00 = 1.0f; p01 = 0.0f; p11 = 1.0f;
        }
        if (k == WROUND && cc == 0) {
            // chunk 0: reset to the exact reference init at t=0
            const float2 pz = *(const float2*)bP;
            x0 = pz.x; x1 = pz.y - pz.x;
            p00 = 1.0f; p01 = 0.0f; p11 = 1.0f;
        }

        // 16 steps, outputs packed into per-warp staging
        char* stg = stgW + l * STG_VSTR;
        #pragma unroll
        for (int g4 = 0; g4 < 4; g4++) {
            const float4 pv = *(const float4*)(bP + g4 * 16);
            const float4 hv = *(const float4*)(bH + g4 * 16);
            const float4 sv = *(const float4*)(bS + g4 * 16);
            steps4(pv, hv, sv, p00, p01, p11, x0, x1, stg + g4 * 32);
        }
        __syncwarp();                          // staging visible warp-wide

        // flush: 8 STG.128, each 4 aligned 128B runs (rows far apart, 4 lines)
        if (k >= WROUND) {
            const int tb = TILE * (k - WROUND);   // 0..496
            #pragma unroll
            for (int j = 0; j < 8; j++) {
                const int v  = j * 4 + (l >> 3);  // vrow: row j, chunk (l>>3)
                const float4 val = *(const float4*)(stgW + v * STG_VSTR + (l & 7) * 16);
                const size_t row = (size_t)(row0 + 8 * w + j);
                float* dst = out + row * (TLEN * 2) + (v & 3) * (CHUNK * 2)
                           + tb * 2 + (l & 7) * 4;
                *(float4*)dst = val;
            }
        }
        __syncwarp();                          // staging reusable next round
    }
}

extern "C" void kernel_launch(void* const* d_in, const int* in_sizes, int n_in,
                              void* d_out, int out_size)
{
    const float* price = (const float*)d_in[0];
    const float* hurst = (const float*)d_in[1];
    const float* sigv  = (const float*)d_in[2];
    float* out = (float*)d_out;

    static bool attr_set = false;
    if (!attr_set) {
        cudaFuncSetAttribute(ekf_kernel, cudaFuncAttributeMaxDynamicSharedMemorySize, SMEM_BYTES);
        attr_set = true;
    }
    ekf_kernel<<<NBLK, BLOCKT, SMEM_BYTES>>>(price, hurst, sigv, out);
}